// round 4
// baseline (speedup 1.0000x reference)
#include <cuda_runtime.h>

#define BB 512      // batch rows
#define NT 1024     // threads per block
#define LL 100      // labels
#define DLEN 100000
#define GAMMA 0.9f

__device__ float g_per_label[LL];
__device__ unsigned int g_cnt = 0;

// One block per label, 1024 threads. Positive rows are compacted; each row's
// j-loops are split across K = NT/n_pos threads (dense assignment). Partials
// are combined through shared memory — no divergent warp collectives.
__global__ __launch_bounds__(NT) void map_loss_fused_kernel(
    const float* __restrict__ y_pred,   // (B, L)
    const float* __restrict__ y_true,   // (B, L)
    const int*   __restrict__ index,    // (B,)
    const float* __restrict__ u_all,    // (L, DLEN)
    const float* __restrict__ u_pos,    // (L, DLEN)
    float* __restrict__ out)
{
    __shared__ float s_fp[BB];
    __shared__ float s_fpp[BB + 8];     // compacted positive fp (+pad)
    __shared__ int   s_prow[BB];        // original row of each positive
    __shared__ float s_ua[BB];
    __shared__ float s_up[BB];
    __shared__ float s_pa[NT];          // per-thread partial S_all
    __shared__ float s_pp[NT];          // per-thread partial S_pos
    __shared__ float s_red[BB];
    __shared__ int   s_wcnt[BB / 32];
    __shared__ int   s_last;

    const int l    = blockIdx.x;
    const int t    = threadIdx.x;
    const int warp = t >> 5;
    const int lane = t & 31;

    // ---- load column l, per-warp positive ballot (warps 0..15 only; warp-uniform branch) ----
    float fp_i = 0.0f;
    bool  pos_i = false;
    unsigned m = 0;
    if (t < BB) {
        fp_i  = y_pred[t * LL + l];
        pos_i = (y_true[t * LL + l] == 1.0f);
        s_fp[t]  = fp_i;
        s_fpp[t] = -1e30f;              // full init: pad/clamped reads give relu=0
        m = __ballot_sync(0xffffffffu, pos_i);
        if (lane == 0) s_wcnt[warp] = __popc(m);
    } else if (t < BB + 8) {
        s_fpp[t] = -1e30f;
    }
    __syncthreads();

    // ---- prefix over warp counts; deterministic compaction ----
    int base = 0, total = 0;
#pragma unroll
    for (int w = 0; w < BB / 32; w++) {
        int c = s_wcnt[w];
        if (w < warp) base += c;
        total += c;
    }
    if (t < BB && pos_i) {
        int off = base + __popc(m & ((1u << lane) - 1u));
        s_fpp[off]  = fp_i;
        s_prow[off] = t;
    }
    const int n_pos = total;                  // >= 1 (row 0 always positive)
    const int np4   = ((n_pos + 7) & ~7) >> 2;  // padded float4 count (multiple of 2)
    __syncthreads();

    // ---- dense work assignment: K chunks per positive row ----
    const int  K      = NT / n_pos;           // >= 2
    const bool active = t < K * n_pos;
    const int  p      = t / K;
    const int  chunk  = t - p * K;
    const int  pc     = active ? p : 0;

    // Prefetch ua/up gathers into shared (latency hides under fma loops)
    if (active && chunk == 0) {
        const int idx = index[s_prow[p]];
        s_ua[p] = u_all[(long long)l * DLEN + idx];
        s_up[p] = u_pos[(long long)l * DLEN + idx];
    }

    // Inactive threads: c = -1e30 -> relu always 0 -> partials are 0.
    const float c = active ? (1.0f - s_fpp[pc]) : -1e30f;

    // ---- S_all partial over this chunk's slice of all 512 fp (128 float4) ----
    const float4* fp4 = reinterpret_cast<const float4*>(s_fp);
    const int la = (128 + K - 1) / K;
    const int ab = chunk * la;
    const int ae = (ab + la < 128) ? (ab + la) : 128;
    float A0 = 0.f, A1 = 0.f, A2 = 0.f, A3 = 0.f;
#pragma unroll 4
    for (int j = ab; j < ae; j++) {
        float4 v = fp4[j];
        float d0 = fmaxf(c + v.x, 0.0f);
        float d1 = fmaxf(c + v.y, 0.0f);
        float d2 = fmaxf(c + v.z, 0.0f);
        float d3 = fmaxf(c + v.w, 0.0f);
        A0 = fmaf(d0, d0, A0);
        A1 = fmaf(d1, d1, A1);
        A2 = fmaf(d2, d2, A2);
        A3 = fmaf(d3, d3, A3);
    }

    // ---- S_pos partial over this chunk's slice of compacted positives ----
    const float4* fpp4 = reinterpret_cast<const float4*>(s_fpp);
    const int lp = (np4 + K - 1) / K;
    const int pb = chunk * lp;
    const int pe = (pb + lp < np4) ? (pb + lp) : np4;
    float P0 = 0.f, P1 = 0.f, P2 = 0.f, P3 = 0.f;
#pragma unroll 4
    for (int j = pb; j < pe; j++) {
        float4 v = fpp4[j];
        float d0 = fmaxf(c + v.x, 0.0f);
        float d1 = fmaxf(c + v.y, 0.0f);
        float d2 = fmaxf(c + v.z, 0.0f);
        float d3 = fmaxf(c + v.w, 0.0f);
        P0 = fmaf(d0, d0, P0);
        P1 = fmaf(d1, d1, P1);
        P2 = fmaf(d2, d2, P2);
        P3 = fmaf(d3, d3, P3);
    }

    s_pa[t] = (A0 + A1) + (A2 + A3);
    s_pp[t] = (P0 + P1) + (P2 + P3);
    __syncthreads();

    // ---- per-row combine + contribution (threads t < n_pos) ----
    float contrib = 0.0f;
    if (t < n_pos) {
        float Sa = 0.f, Sp = 0.f;
        const int b0 = t * K;
        for (int k = 0; k < K; k++) {
            Sa += s_pa[b0 + k];
            Sp += s_pp[b0 + k];
        }
        const float ua = s_ua[t];
        const float up = s_up[t];
        const float ua_new = (1.0f - GAMMA) * ua + GAMMA * (Sa * (1.0f / (float)BB));
        const float up_new = (1.0f - GAMMA) * up + GAMMA * (Sp * (1.0f / (float)BB));
        contrib = (up_new * Sa - ua_new * Sp) / (ua_new * ua_new);
    }
    if (t < BB) s_red[t] = (t < n_pos) ? contrib : 0.0f;
    __syncthreads();

    // ---- block reduction over 512 slots (fixed order -> deterministic) ----
#pragma unroll
    for (int s = BB / 2; s > 32; s >>= 1) {
        if (t < s) s_red[t] += s_red[t + s];
        __syncthreads();
    }
    if (t < 32) {
        float v = s_red[t] + s_red[t + 32];
#pragma unroll
        for (int off = 16; off > 0; off >>= 1)
            v += __shfl_down_sync(0xffffffffu, v, off);
        if (t == 0) {
            g_per_label[l] = v / ((float)n_pos * (float)BB);
            __threadfence();
            unsigned old = atomicAdd(&g_cnt, 1u);
            s_last = (old == LL - 1) ? 1 : 0;
        }
    }
    __syncthreads();

    // ---- last block folds the 100 per-label values with one warp ----
    if (s_last && warp == 0) {
        __threadfence();
        volatile float* gp = g_per_label;
        float v = 0.0f;
#pragma unroll
        for (int j = 0; j < 4; j++) {       // lanes cover 0..127 (>= LL)
            int idx = lane + j * 32;
            if (idx < LL) v += gp[idx];
        }
#pragma unroll
        for (int off = 16; off > 0; off >>= 1)
            v += __shfl_down_sync(0xffffffffu, v, off);
        if (lane == 0) {
            out[0] = v / (float)LL;
            g_cnt = 0;                       // reset for next graph replay
        }
    }
}

extern "C" void kernel_launch(void* const* d_in, const int* in_sizes, int n_in,
                              void* d_out, int out_size) {
    const float* y_pred = (const float*)d_in[0];
    const float* y_true = (const float*)d_in[1];
    const int*   index  = (const int*)d_in[2];
    const float* u_all  = (const float*)d_in[3];
    const float* u_pos  = (const float*)d_in[4];
    float* out = (float*)d_out;

    map_loss_fused_kernel<<<LL, NT>>>(y_pred, y_true, index, u_all, u_pos, out);
}

// round 5
// speedup vs baseline: 1.7910x; 1.7910x over previous
#include <cuda_runtime.h>

#define BB 512      // batch rows = threads per block
#define NW 16       // warps per block
#define LL 100      // labels
#define DLEN 100000
#define GAMMA 0.9f

__device__ float g_per_label[LL];
__device__ unsigned int g_cnt = 0;

// One block per label, 512 threads. Positive rows compacted; 2 threads per
// positive row (j-range halves) when 2*n_pos <= 512. Warps beyond the active
// range skip the mainloop entirely (warp-uniform branch).
__global__ __launch_bounds__(BB) void map_loss_fused_kernel(
    const float* __restrict__ y_pred,   // (B, L)
    const float* __restrict__ y_true,   // (B, L)
    const int*   __restrict__ index,    // (B,)
    const float* __restrict__ u_all,    // (L, DLEN)
    const float* __restrict__ u_pos,    // (L, DLEN)
    float* __restrict__ out)
{
    __shared__ float s_fp[BB];
    __shared__ float s_fpp[BB + 8];     // compacted positive fp (+pad)
    __shared__ int   s_prow[BB];        // original row of each positive slot
    __shared__ float s_ua[BB];          // gathered u_all, indexed by ROW
    __shared__ float s_up[BB];          // gathered u_pos, indexed by ROW
    __shared__ int   s_wcnt[NW];
    __shared__ float s_wsum[NW];
    __shared__ int   s_last;

    const int l    = blockIdx.x;
    const int t    = threadIdx.x;
    const int warp = t >> 5;
    const int lane = t & 31;

    // ---- load column l; issue u gathers for own row IMMEDIATELY (overlap) ----
    const float fp_i  = y_pred[t * LL + l];
    const bool  pos_i = (y_true[t * LL + l] == 1.0f);
    s_fp[t]  = fp_i;
    s_fpp[t] = -1e30f;                  // pad/clamped reads -> relu = 0
    if (t < 8) s_fpp[BB + t] = -1e30f;
    if (pos_i) {
        const int idx = index[t];
        s_ua[t] = u_all[(long long)l * DLEN + idx];
        s_up[t] = u_pos[(long long)l * DLEN + idx];
    }

    const unsigned m = __ballot_sync(0xffffffffu, pos_i);
    if (lane == 0) s_wcnt[warp] = __popc(m);
    __syncthreads();

    // ---- prefix over warp counts; deterministic compaction ----
    int base = 0, total = 0;
#pragma unroll
    for (int w = 0; w < NW; w++) {
        int c = s_wcnt[w];
        if (w < warp) base += c;
        total += c;
    }
    if (pos_i) {
        const int off = base + __popc(m & ((1u << lane) - 1u));
        s_fpp[off]  = fp_i;
        s_prow[off] = t;
    }
    const int n_pos = total;                      // >= 1 (row 0 all-positive)
    const int np4   = ((n_pos + 7) & ~7) >> 2;    // padded float4 count (even)
    __syncthreads();

    // ---- work assignment (block-uniform) ----
    const bool split2    = (2 * n_pos <= BB);
    const int  n_act_thr = split2 ? (2 * n_pos) : n_pos;
    const int  n_act_wrp = (n_act_thr + 31) >> 5;

    float contrib = 0.0f;

    if (warp < n_act_wrp) {            // WARP-UNIFORM: idle warps skip all of this
        const bool act  = t < n_act_thr;
        const int  p    = split2 ? (t >> 1) : t;  // <= 255 or <= 511, in range
        const int  half = split2 ? (t & 1) : 0;
        const float c   = act ? (1.0f - s_fpp[p]) : -1e30f;

        // S_all over this thread's half of the 512 fp values (128 float4)
        const float4* fp4 = reinterpret_cast<const float4*>(s_fp);
        float A0 = 0.f, A1 = 0.f, A2 = 0.f, A3 = 0.f;
        if (split2) {
            const int ab = half * 64;
#pragma unroll 4
            for (int j = ab; j < ab + 64; j++) {
                float4 v = fp4[j];
                float d0 = fmaxf(c + v.x, 0.0f);
                float d1 = fmaxf(c + v.y, 0.0f);
                float d2 = fmaxf(c + v.z, 0.0f);
                float d3 = fmaxf(c + v.w, 0.0f);
                A0 = fmaf(d0, d0, A0); A1 = fmaf(d1, d1, A1);
                A2 = fmaf(d2, d2, A2); A3 = fmaf(d3, d3, A3);
            }
        } else {
#pragma unroll 4
            for (int j = 0; j < 128; j++) {
                float4 v = fp4[j];
                float d0 = fmaxf(c + v.x, 0.0f);
                float d1 = fmaxf(c + v.y, 0.0f);
                float d2 = fmaxf(c + v.z, 0.0f);
                float d3 = fmaxf(c + v.w, 0.0f);
                A0 = fmaf(d0, d0, A0); A1 = fmaf(d1, d1, A1);
                A2 = fmaf(d2, d2, A2); A3 = fmaf(d3, d3, A3);
            }
        }
        float S_all = (A0 + A1) + (A2 + A3);

        // S_pos over this thread's half of the compacted positives
        const float4* fpp4 = reinterpret_cast<const float4*>(s_fpp);
        int pb, pe;
        if (split2) { const int h = np4 >> 1; pb = half * h; pe = pb + h; }
        else        { pb = 0; pe = np4; }
        float P0 = 0.f, P1 = 0.f, P2 = 0.f, P3 = 0.f;
#pragma unroll 4
        for (int j = pb; j < pe; j++) {
            float4 v = fpp4[j];
            float d0 = fmaxf(c + v.x, 0.0f);
            float d1 = fmaxf(c + v.y, 0.0f);
            float d2 = fmaxf(c + v.z, 0.0f);
            float d3 = fmaxf(c + v.w, 0.0f);
            P0 = fmaf(d0, d0, P0); P1 = fmaf(d1, d1, P1);
            P2 = fmaf(d2, d2, P2); P3 = fmaf(d3, d3, P3);
        }
        float S_pos = (P0 + P1) + (P2 + P3);

        // Combine halves: executed by ALL 32 lanes of this warp (uniform).
        if (split2) {
            S_all += __shfl_xor_sync(0xffffffffu, S_all, 1);
            S_pos += __shfl_xor_sync(0xffffffffu, S_pos, 1);
        }

        if (act && half == 0) {
            const int   row = s_prow[p];
            const float ua  = s_ua[row];
            const float up  = s_up[row];
            const float ua_new = (1.0f - GAMMA) * ua + GAMMA * (S_all * (1.0f / (float)BB));
            const float up_new = (1.0f - GAMMA) * up + GAMMA * (S_pos * (1.0f / (float)BB));
            contrib = (up_new * S_all - ua_new * S_pos) / (ua_new * ua_new);
        }
    }

    // ---- reduction: warp shuffle + one cross-warp fold (deterministic) ----
    float v = contrib;
#pragma unroll
    for (int off = 16; off > 0; off >>= 1)
        v += __shfl_down_sync(0xffffffffu, v, off);
    if (lane == 0) s_wsum[warp] = v;
    __syncthreads();

    if (warp == 0) {
        float v2 = (lane < NW) ? s_wsum[lane] : 0.0f;
#pragma unroll
        for (int off = 16; off > 0; off >>= 1)
            v2 += __shfl_down_sync(0xffffffffu, v2, off);
        if (lane == 0) {
            g_per_label[l] = v2 / ((float)n_pos * (float)BB);
            __threadfence();
            const unsigned old = atomicAdd(&g_cnt, 1u);
            s_last = (old == LL - 1) ? 1 : 0;
        }
    }
    __syncthreads();

    // ---- last block folds the 100 per-label values (fixed order) ----
    if (s_last && warp == 0) {
        __threadfence();
        volatile float* gp = g_per_label;
        float a = 0.0f;
#pragma unroll
        for (int j = 0; j < 4; j++) {
            const int idx = lane + j * 32;
            if (idx < LL) a += gp[idx];
        }
#pragma unroll
        for (int off = 16; off > 0; off >>= 1)
            a += __shfl_down_sync(0xffffffffu, a, off);
        if (lane == 0) {
            out[0] = a / (float)LL;
            g_cnt = 0;                 // reset for next graph replay
        }
    }
}

extern "C" void kernel_launch(void* const* d_in, const int* in_sizes, int n_in,
                              void* d_out, int out_size) {
    const float* y_pred = (const float*)d_in[0];
    const float* y_true = (const float*)d_in[1];
    const int*   index  = (const int*)d_in[2];
    const float* u_all  = (const float*)d_in[3];
    const float* u_pos  = (const float*)d_in[4];
    float* out = (float*)d_out;

    map_loss_fused_kernel<<<LL, BB>>>(y_pred, y_true, index, u_all, u_pos, out);
}